// round 5
// baseline (speedup 1.0000x reference)
#include <cuda_runtime.h>
#include <cstdint>

// Problem constants
namespace {
constexpr int Bb = 8, Ss = 4096, Dh = 1024;
constexpr int M  = Bb * Ss;   // 32768
constexpr int K  = 1024;
constexpr int BM = 128, BN = 64, BK = 32;
constexpr int LDSR = BK + 4;          // 36 floats/row: conflict-free, 16B-aligned rows
constexpr int XSZ  = BM * LDSR;       // 4608 floats
constexpr int WSZ  = BN * LDSR;       // 2304 floats
}

// Scratch: (a_t, b_t) interleaved pairs, and the scanned hidden state h.
__device__ float2 g_ab[(size_t)M * Dh];   // 268 MB
__device__ float  g_h [(size_t)M * Dh];   // 134 MB

__device__ __forceinline__ uint32_t f2tf(float f) {
    uint32_t r;
    asm("cvt.rna.tf32.f32 %0, %1;" : "=r"(r) : "f"(f));
    return r;
}

__device__ __forceinline__ void cp16(float* sdst, const float* gsrc) {
    uint32_t s = (uint32_t)__cvta_generic_to_shared(sdst);
    asm volatile("cp.async.cg.shared.global [%0], [%1], 16;" :: "r"(s), "l"(gsrc));
}

__device__ __forceinline__ void mma8(float* c, const uint32_t* a, const uint32_t* b) {
    asm volatile(
        "mma.sync.aligned.m16n8k8.row.col.f32.tf32.tf32.f32 "
        "{%0,%1,%2,%3}, {%4,%5,%6,%7}, {%8,%9}, {%0,%1,%2,%3};"
        : "+f"(c[0]), "+f"(c[1]), "+f"(c[2]), "+f"(c[3])
        : "r"(a[0]), "r"(a[1]), "r"(a[2]), "r"(a[3]), "r"(b[0]), "r"(b[1]));
}

__device__ __forceinline__ float sigm(float x) { return 1.f / (1.f + __expf(-x)); }

// DUAL=true : A=x, computes k (W1=Wz) and h_tilde (W2=Wh), fused nonlinearity,
//             writes (a, b) pairs to g_ab.
// DUAL=false: A=g_h, computes out = h*Wo^T + bo into outF.
template <bool DUAL>
__global__ void __launch_bounds__(256)
gemm_kernel(const float* __restrict__ Ax,
            const float* __restrict__ W1, const float* __restrict__ b1,
            const float* __restrict__ W2, const float* __restrict__ b2,
            float* __restrict__ outF)
{
    extern __shared__ float sm[];
    const int STAGE = XSZ + (DUAL ? 2 : 1) * WSZ;

    const int tid  = threadIdx.x;
    const int m0   = blockIdx.x * BM;
    const int n0   = blockIdx.y * BN;
    const int lane = tid & 31;
    const int warp = tid >> 5;
    const int wm   = warp & 3;    // 4 warps along M (32 rows each)
    const int wn   = warp >> 2;   // 2 warps along N (32 cols each)
    const int gr   = lane >> 2;   // 0..7
    const int gc   = lane & 3;    // 0..3

    const float* A = DUAL ? Ax : (const float*)g_h;

    float accZ[2][4][4];
    float accH[2][4][4];
#pragma unroll
    for (int i = 0; i < 2; ++i)
#pragma unroll
        for (int j = 0; j < 4; ++j)
#pragma unroll
            for (int r = 0; r < 4; ++r) { accZ[i][j][r] = 0.f; if (DUAL) accH[i][j][r] = 0.f; }

    auto load_stage = [&](int kt, int buf) {
        float* xs  = sm + buf * STAGE;
        float* w1s = xs + XSZ;
        float* w2s = w1s + WSZ;
        const int ko = kt * BK;
#pragma unroll
        for (int i = 0; i < 4; ++i) {
            int idx = tid + i * 256;            // 0..1023
            int r = idx >> 3, c = (idx & 7) * 4;
            cp16(xs + r * LDSR + c, A + (size_t)(m0 + r) * K + ko + c);
        }
#pragma unroll
        for (int i = 0; i < 2; ++i) {
            int idx = tid + i * 256;            // 0..511
            int r = idx >> 3, c = (idx & 7) * 4;
            cp16(w1s + r * LDSR + c, W1 + (size_t)(n0 + r) * K + ko + c);
            if (DUAL)
                cp16(w2s + r * LDSR + c, W2 + (size_t)(n0 + r) * K + ko + c);
        }
        asm volatile("cp.async.commit_group;");
    };

    constexpr int NT = K / BK;   // 32
    load_stage(0, 0);

    for (int kt = 0; kt < NT; ++kt) {
        const int cur = kt & 1;
        if (kt + 1 < NT) {
            load_stage(kt + 1, cur ^ 1);
            asm volatile("cp.async.wait_group 1;");
        } else {
            asm volatile("cp.async.wait_group 0;");
        }
        __syncthreads();

        const float* xs  = sm + cur * STAGE;
        const float* w1s = xs + XSZ;
        const float* w2s = w1s + WSZ;
#pragma unroll
        for (int ks = 0; ks < BK / 8; ++ks) {
            const int kc = ks * 8;
            uint32_t af[2][4];
#pragma unroll
            for (int i = 0; i < 2; ++i) {
                const float* p = xs + (wm * 32 + i * 16 + gr) * LDSR + kc + gc;
                af[i][0] = f2tf(p[0]);
                af[i][1] = f2tf(p[8 * LDSR]);
                af[i][2] = f2tf(p[4]);
                af[i][3] = f2tf(p[8 * LDSR + 4]);
            }
#pragma unroll
            for (int j = 0; j < 4; ++j) {
                const float* p1 = w1s + (wn * 32 + j * 8 + gr) * LDSR + kc + gc;
                uint32_t bf1[2] = { f2tf(p1[0]), f2tf(p1[4]) };
#pragma unroll
                for (int i = 0; i < 2; ++i) mma8(accZ[i][j], af[i], bf1);
                if (DUAL) {
                    const float* p2 = w2s + (wn * 32 + j * 8 + gr) * LDSR + kc + gc;
                    uint32_t bf2[2] = { f2tf(p2[0]), f2tf(p2[4]) };
#pragma unroll
                    for (int i = 0; i < 2; ++i) mma8(accH[i][j], af[i], bf2);
                }
            }
        }
        __syncthreads();
    }

    // Epilogue
#pragma unroll
    for (int i = 0; i < 2; ++i)
#pragma unroll
        for (int j = 0; j < 4; ++j)
#pragma unroll
            for (int p = 0; p < 2; ++p) {
                const int row = m0 + wm * 32 + i * 16 + gr + p * 8;
                const int col = n0 + wn * 32 + j * 8 + gc * 2;
                if (DUAL) {
                    float kz0 = accZ[i][j][2 * p + 0] + __ldg(&b1[col]);
                    float kz1 = accZ[i][j][2 * p + 1] + __ldg(&b1[col + 1]);
                    float kh0 = accH[i][j][2 * p + 0] + __ldg(&b2[col]);
                    float kh1 = accH[i][j][2 * p + 1] + __ldg(&b2[col + 1]);
                    // g(x) = x>=0 ? x+0.5 : sigmoid(x)   (== exp(log_g))
                    float g0 = (kh0 >= 0.f) ? (kh0 + 0.5f) : sigm(kh0);
                    float g1 = (kh1 >= 0.f) ? (kh1 + 0.5f) : sigm(kh1);
                    float4 o;
                    o.x = sigm(-kz0);            // a_t = 1 - z_t
                    o.y = sigm(kz0) * g0;        // b_t = z_t * g_t
                    o.z = sigm(-kz1);
                    o.w = sigm(kz1) * g1;
                    *reinterpret_cast<float4*>(&g_ab[(size_t)row * Dh + col]) = o;
                } else {
                    float2 o;
                    o.x = accZ[i][j][2 * p + 0] + __ldg(&b1[col]);
                    o.y = accZ[i][j][2 * p + 1] + __ldg(&b1[col + 1]);
                    *reinterpret_cast<float2*>(&outF[(size_t)row * Dh + col]) = o;
                }
            }
}

// One thread per (batch, hidden) sequence: h_t = a_t * h_{t-1} + b_t
__global__ void scan_kernel()
{
    const int g  = blockIdx.x * blockDim.x + threadIdx.x;  // 0..8191
    const int b  = g >> 10;
    const int hh = g & 1023;
    const size_t base = (size_t)b * Ss * Dh + hh;
    float h = 0.f;
#pragma unroll 4
    for (int s = 0; s < Ss; ++s) {
        const size_t idx = base + (size_t)s * Dh;
        float2 v = g_ab[idx];
        h = fmaf(v.x, h, v.y);
        g_h[idx] = h;
    }
}

extern "C" void kernel_launch(void* const* d_in, const int* in_sizes, int n_in,
                              void* d_out, int out_size)
{
    const float* x  = (const float*)d_in[0];
    const float* Wz = (const float*)d_in[1];
    const float* bz = (const float*)d_in[2];
    const float* Wh = (const float*)d_in[3];
    const float* bh = (const float*)d_in[4];
    const float* Wo = (const float*)d_in[5];
    const float* bo = (const float*)d_in[6];
    float* out = (float*)d_out;

    const int smem_dual   = 2 * (XSZ + 2 * WSZ) * 4;  // 73728 B
    const int smem_single = 2 * (XSZ + 1 * WSZ) * 4;  // 55296 B
    cudaFuncSetAttribute(gemm_kernel<true>,  cudaFuncAttributeMaxDynamicSharedMemorySize, smem_dual);
    cudaFuncSetAttribute(gemm_kernel<false>, cudaFuncAttributeMaxDynamicSharedMemorySize, smem_single);

    dim3 grid(M / BM, Dh / BN);   // 256 x 16

    // 1) fused dual GEMM + gate nonlinearities -> (a, b) pairs
    gemm_kernel<true><<<grid, 256, smem_dual>>>(x, Wz, bz, Wh, bh, nullptr);
    // 2) sequential scan along S, one thread per (b, h)
    scan_kernel<<<(Bb * Dh) / 256, 256>>>();
    // 3) output projection with bias
    gemm_kernel<false><<<grid, 256, smem_single>>>(nullptr, Wo, bo, nullptr, nullptr, out);
}

// round 9
// speedup vs baseline: 2.1954x; 2.1954x over previous
#include <cuda_runtime.h>
#include <cstdint>

// Problem constants
namespace {
constexpr int Bb = 8, Ss = 4096, Dh = 1024;
constexpr int M  = Bb * Ss;   // 32768
constexpr int K  = 1024;
constexpr int BM = 128, BN = 64, BK = 32;
constexpr int LDSR = BK + 4;          // 36 floats/row: conflict-free, 16B-aligned rows
constexpr int XSZ  = BM * LDSR;       // 4608 floats
constexpr int WSZ  = BN * LDSR;       // 2304 floats
// Scan chunking
constexpr int NC = 64;                // chunks per sequence
constexpr int CL = Ss / NC;           // 64 steps per chunk
constexpr int NSEQ = Bb * Dh;         // 8192 independent sequences
}

// Scratch
__device__ float2 g_ab[(size_t)M * Dh];        // (a_t, b_t) pairs, 268 MB
__device__ float  g_h [(size_t)M * Dh];        // scanned h (tf32-rounded), 134 MB
__device__ float  g_xr[(size_t)M * K];         // tf32-rounded x, 134 MB
__device__ float  g_wzr[(size_t)Dh * K];       // tf32-rounded weights
__device__ float  g_whr[(size_t)Dh * K];
__device__ float  g_wor[(size_t)Dh * K];
__device__ float2 g_comp [(size_t)NC * NSEQ];  // per-chunk (A, B) composites
__device__ float  g_carry[(size_t)NC * NSEQ];  // h at each chunk start

__device__ __forceinline__ uint32_t f2tf(float f) {
    uint32_t r;
    asm("cvt.rna.tf32.f32 %0, %1;" : "=r"(r) : "f"(f));
    return r;
}

__device__ __forceinline__ void cp16(const float* sdst, const float* gsrc) {
    uint32_t s = (uint32_t)__cvta_generic_to_shared(sdst);
    asm volatile("cp.async.cg.shared.global [%0], [%1], 16;" :: "r"(s), "l"(gsrc));
}

__device__ __forceinline__ void mma8(float* c, const uint32_t* a, const uint32_t* b) {
    asm volatile(
        "mma.sync.aligned.m16n8k8.row.col.f32.tf32.tf32.f32 "
        "{%0,%1,%2,%3}, {%4,%5,%6,%7}, {%8,%9}, {%0,%1,%2,%3};"
        : "+f"(c[0]), "+f"(c[1]), "+f"(c[2]), "+f"(c[3])
        : "r"(a[0]), "r"(a[1]), "r"(a[2]), "r"(a[3]), "r"(b[0]), "r"(b[1]));
}

__device__ __forceinline__ float sigm(float x) { return 1.f / (1.f + __expf(-x)); }

// Elementwise tf32 rounding pass (vectorized).
__global__ void __launch_bounds__(256) round_kernel(const float4* __restrict__ in,
                                                    float4* __restrict__ out, int n4)
{
    int i = blockIdx.x * blockDim.x + threadIdx.x;
    if (i >= n4) return;
    float4 v = in[i];
    v.x = __uint_as_float(f2tf(v.x));
    v.y = __uint_as_float(f2tf(v.y));
    v.z = __uint_as_float(f2tf(v.z));
    v.w = __uint_as_float(f2tf(v.w));
    out[i] = v;
}

// DUAL=true : A=g_xr, computes k (W1=Wz) and h_tilde (W2=Wh), fused nonlinearity,
//             writes (a, b) pairs to g_ab.
// DUAL=false: A=g_h, computes out = h*Wo^T + bo into outF.
// All operand matrices are pre-rounded to tf32 -> no converts in the inner loop.
template <bool DUAL>
__global__ void __launch_bounds__(256)
gemm_kernel(const float* __restrict__ b1, const float* __restrict__ b2,
            float* __restrict__ outF)
{
    extern __shared__ float sm[];
    const int STAGE = XSZ + (DUAL ? 2 : 1) * WSZ;

    const int tid  = threadIdx.x;
    const int m0   = blockIdx.x * BM;
    const int n0   = blockIdx.y * BN;
    const int lane = tid & 31;
    const int warp = tid >> 5;
    const int wm   = warp & 3;    // 4 warps along M (32 rows each)
    const int wn   = warp >> 2;   // 2 warps along N (32 cols each)
    const int gr   = lane >> 2;   // 0..7
    const int gc   = lane & 3;    // 0..3

    const float* A  = DUAL ? (const float*)g_xr : (const float*)g_h;
    const float* W1 = DUAL ? (const float*)g_wzr : (const float*)g_wor;
    const float* W2 = (const float*)g_whr;

    float accZ[2][4][4];
    float accH[2][4][4];
#pragma unroll
    for (int i = 0; i < 2; ++i)
#pragma unroll
        for (int j = 0; j < 4; ++j)
#pragma unroll
            for (int r = 0; r < 4; ++r) { accZ[i][j][r] = 0.f; if (DUAL) accH[i][j][r] = 0.f; }

    auto load_stage = [&](int kt, int buf) {
        float* xs  = sm + buf * STAGE;
        float* w1s = xs + XSZ;
        float* w2s = w1s + WSZ;
        const int ko = kt * BK;
#pragma unroll
        for (int i = 0; i < 4; ++i) {
            int idx = tid + i * 256;            // 0..1023
            int r = idx >> 3, c = (idx & 7) * 4;
            cp16(xs + r * LDSR + c, A + (size_t)(m0 + r) * K + ko + c);
        }
#pragma unroll
        for (int i = 0; i < 2; ++i) {
            int idx = tid + i * 256;            // 0..511
            int r = idx >> 3, c = (idx & 7) * 4;
            cp16(w1s + r * LDSR + c, W1 + (size_t)(n0 + r) * K + ko + c);
            if (DUAL)
                cp16(w2s + r * LDSR + c, W2 + (size_t)(n0 + r) * K + ko + c);
        }
        asm volatile("cp.async.commit_group;");
    };

    constexpr int NT = K / BK;   // 32
    load_stage(0, 0);

    for (int kt = 0; kt < NT; ++kt) {
        const int cur = kt & 1;
        if (kt + 1 < NT) {
            load_stage(kt + 1, cur ^ 1);
            asm volatile("cp.async.wait_group 1;");
        } else {
            asm volatile("cp.async.wait_group 0;");
        }
        __syncthreads();

        const uint32_t* xs  = reinterpret_cast<const uint32_t*>(sm + cur * STAGE);
        const uint32_t* w1s = xs + XSZ;
        const uint32_t* w2s = w1s + WSZ;
#pragma unroll
        for (int ks = 0; ks < BK / 8; ++ks) {
            const int kc = ks * 8;
            uint32_t af[2][4];
#pragma unroll
            for (int i = 0; i < 2; ++i) {
                const uint32_t* p = xs + (wm * 32 + i * 16 + gr) * LDSR + kc + gc;
                af[i][0] = p[0];
                af[i][1] = p[8 * LDSR];
                af[i][2] = p[4];
                af[i][3] = p[8 * LDSR + 4];
            }
#pragma unroll
            for (int j = 0; j < 4; ++j) {
                const uint32_t* p1 = w1s + (wn * 32 + j * 8 + gr) * LDSR + kc + gc;
                uint32_t bf1[2] = { p1[0], p1[4] };
#pragma unroll
                for (int i = 0; i < 2; ++i) mma8(accZ[i][j], af[i], bf1);
                if (DUAL) {
                    const uint32_t* p2 = w2s + (wn * 32 + j * 8 + gr) * LDSR + kc + gc;
                    uint32_t bf2[2] = { p2[0], p2[4] };
#pragma unroll
                    for (int i = 0; i < 2; ++i) mma8(accH[i][j], af[i], bf2);
                }
            }
        }
        __syncthreads();
    }

    // Epilogue
#pragma unroll
    for (int i = 0; i < 2; ++i)
#pragma unroll
        for (int j = 0; j < 4; ++j)
#pragma unroll
            for (int p = 0; p < 2; ++p) {
                const int row = m0 + wm * 32 + i * 16 + gr + p * 8;
                const int col = n0 + wn * 32 + j * 8 + gc * 2;
                if (DUAL) {
                    float kz0 = accZ[i][j][2 * p + 0] + __ldg(&b1[col]);
                    float kz1 = accZ[i][j][2 * p + 1] + __ldg(&b1[col + 1]);
                    float kh0 = accH[i][j][2 * p + 0] + __ldg(&b2[col]);
                    float kh1 = accH[i][j][2 * p + 1] + __ldg(&b2[col + 1]);
                    // g(x) = x>=0 ? x+0.5 : sigmoid(x)   (== exp(log_g))
                    float g0 = (kh0 >= 0.f) ? (kh0 + 0.5f) : sigm(kh0);
                    float g1 = (kh1 >= 0.f) ? (kh1 + 0.5f) : sigm(kh1);
                    float4 o;
                    o.x = sigm(-kz0);            // a_t = 1 - z_t
                    o.y = sigm(kz0) * g0;        // b_t = z_t * g_t
                    o.z = sigm(-kz1);
                    o.w = sigm(kz1) * g1;
                    *reinterpret_cast<float4*>(&g_ab[(size_t)row * Dh + col]) = o;
                } else {
                    float2 o;
                    o.x = accZ[i][j][2 * p + 0] + __ldg(&b1[col]);
                    o.y = accZ[i][j][2 * p + 1] + __ldg(&b1[col + 1]);
                    *reinterpret_cast<float2*>(&outF[(size_t)row * Dh + col]) = o;
                }
            }
}

// ---- Chunked parallel scan: h_t = a_t * h_{t-1} + b_t ----
// P1: each thread reduces one (sequence, chunk) to the composite (A, B).
__global__ void __launch_bounds__(256) scan_p1()
{
    const int t     = blockIdx.x * blockDim.x + threadIdx.x;   // 0..NC*NSEQ-1
    const int bh    = t & (NSEQ - 1);                          // low bits -> coalesced over h
    const int chunk = t >> 13;
    const int b  = bh >> 10;
    const int hh = bh & 1023;
    const size_t base = ((size_t)b * Ss + (size_t)chunk * CL) * Dh + hh;
    float A = 1.f, Bv = 0.f;
#pragma unroll 8
    for (int s = 0; s < CL; ++s) {
        float2 v = g_ab[base + (size_t)s * Dh];
        A  *= v.x;
        Bv  = fmaf(v.x, Bv, v.y);
    }
    g_comp[(size_t)chunk * NSEQ + bh] = make_float2(A, Bv);
}

// P2: per-sequence scan over the NC chunk composites; store carry-in per chunk.
__global__ void __launch_bounds__(256) scan_p2()
{
    const int bh = blockIdx.x * blockDim.x + threadIdx.x;      // 0..NSEQ-1
    float h = 0.f;
#pragma unroll
    for (int c = 0; c < NC; ++c) {
        const size_t idx = (size_t)c * NSEQ + bh;
        float2 cmp = g_comp[idx];
        g_carry[idx] = h;
        h = fmaf(cmp.x, h, cmp.y);
    }
}

// P3: re-scan each chunk from its carry; write h (pre-rounded to tf32 for GEMM2).
__global__ void __launch_bounds__(256) scan_p3()
{
    const int t     = blockIdx.x * blockDim.x + threadIdx.x;
    const int bh    = t & (NSEQ - 1);
    const int chunk = t >> 13;
    const int b  = bh >> 10;
    const int hh = bh & 1023;
    const size_t base = ((size_t)b * Ss + (size_t)chunk * CL) * Dh + hh;
    float h = g_carry[(size_t)chunk * NSEQ + bh];
#pragma unroll 8
    for (int s = 0; s < CL; ++s) {
        const size_t idx = base + (size_t)s * Dh;
        float2 v = g_ab[idx];
        h = fmaf(v.x, h, v.y);
        g_h[idx] = __uint_as_float(f2tf(h));
    }
}

extern "C" void kernel_launch(void* const* d_in, const int* in_sizes, int n_in,
                              void* d_out, int out_size)
{
    const float* x  = (const float*)d_in[0];
    const float* Wz = (const float*)d_in[1];
    const float* bz = (const float*)d_in[2];
    const float* Wh = (const float*)d_in[3];
    const float* bh = (const float*)d_in[4];
    const float* Wo = (const float*)d_in[5];
    const float* bo = (const float*)d_in[6];
    float* out = (float*)d_out;

    const int smem_dual   = 2 * (XSZ + 2 * WSZ) * 4;  // 73728 B
    const int smem_single = 2 * (XSZ + 1 * WSZ) * 4;  // 55296 B
    cudaFuncSetAttribute(gemm_kernel<true>,  cudaFuncAttributeMaxDynamicSharedMemorySize, smem_dual);
    cudaFuncSetAttribute(gemm_kernel<false>, cudaFuncAttributeMaxDynamicSharedMemorySize, smem_single);

    // 0) pre-round operands to tf32 (removes all CVTs from GEMM inner loops)
    {
        float* xr;  cudaGetSymbolAddress((void**)&xr,  g_xr);
        float* wzr; cudaGetSymbolAddress((void**)&wzr, g_wzr);
        float* whr; cudaGetSymbolAddress((void**)&whr, g_whr);
        float* wor; cudaGetSymbolAddress((void**)&wor, g_wor);
        const int nx4 = (M * K) / 4;
        const int nw4 = (Dh * K) / 4;
        round_kernel<<<(nx4 + 255) / 256, 256>>>((const float4*)x,  (float4*)xr,  nx4);
        round_kernel<<<(nw4 + 255) / 256, 256>>>((const float4*)Wz, (float4*)wzr, nw4);
        round_kernel<<<(nw4 + 255) / 256, 256>>>((const float4*)Wh, (float4*)whr, nw4);
        round_kernel<<<(nw4 + 255) / 256, 256>>>((const float4*)Wo, (float4*)wor, nw4);
    }

    dim3 grid(M / BM, Dh / BN);   // 256 x 16

    // 1) fused dual GEMM + gate nonlinearities -> (a, b) pairs
    gemm_kernel<true><<<grid, 256, smem_dual>>>(bz, bh, nullptr);

    // 2) chunked parallel scan
    scan_p1<<<(NC * NSEQ) / 256, 256>>>();
    scan_p2<<<NSEQ / 256, 256>>>();
    scan_p3<<<(NC * NSEQ) / 256, 256>>>();

    // 3) output projection with bias
    gemm_kernel<false><<<grid, 256, smem_single>>>(bo, nullptr, out);
}

// round 11
// speedup vs baseline: 3.8949x; 1.7741x over previous
#include <cuda_runtime.h>
#include <cuda_fp16.h>
#include <cstdint>

// Problem constants
namespace {
constexpr int Bb = 8, Ss = 4096, Dh = 1024;
constexpr int M  = Bb * Ss;   // 32768
constexpr int K  = 1024;
// GEMM tiling (fp16 mma.m16n8k16 + ldmatrix)
constexpr int BM = 128, BN = 64, BKH = 32;    // BKH halves per chunk = 64B rows
constexpr int NT = K / BKH;                   // 32 chunks
constexpr int STAGES = 4;
constexpr int TILEA = BM * BKH * 2;           // 8192 B
constexpr int TILEB = BN * BKH * 2;           // 4096 B
// Scan chunking
constexpr int NC = 64;
constexpr int CL = Ss / NC;
constexpr int NSEQ = Bb * Dh;                 // 8192
}

// Scratch
__device__ float2 g_ab[(size_t)M * Dh];        // (a_t, b_t) pairs, 268 MB
__device__ __half g_xh [(size_t)M * K];        // fp16 x
__device__ __half g_hh [(size_t)M * Dh];       // fp16 scanned h
__device__ __half g_wzh[(size_t)Dh * K];
__device__ __half g_whh[(size_t)Dh * K];
__device__ __half g_woh[(size_t)Dh * K];
__device__ float2 g_comp [(size_t)NC * NSEQ];
__device__ float  g_carry[(size_t)NC * NSEQ];

__device__ __forceinline__ float sigm(float x) { return 1.f / (1.f + __expf(-x)); }

__device__ __forceinline__ void cp16s(uint32_t saddr, const void* gsrc) {
    asm volatile("cp.async.cg.shared.global [%0], [%1], 16;" :: "r"(saddr), "l"(gsrc));
}

__device__ __forceinline__ void ldmx4(uint32_t* r, uint32_t a) {
    asm volatile("ldmatrix.sync.aligned.m8n8.x4.shared.b16 {%0,%1,%2,%3}, [%4];"
        : "=r"(r[0]), "=r"(r[1]), "=r"(r[2]), "=r"(r[3]) : "r"(a));
}

__device__ __forceinline__ void mma16(float* c, const uint32_t* a, const uint32_t* b) {
    asm volatile(
        "mma.sync.aligned.m16n8k16.row.col.f32.f16.f16.f32 "
        "{%0,%1,%2,%3}, {%4,%5,%6,%7}, {%8,%9}, {%0,%1,%2,%3};"
        : "+f"(c[0]), "+f"(c[1]), "+f"(c[2]), "+f"(c[3])
        : "r"(a[0]), "r"(a[1]), "r"(a[2]), "r"(a[3]), "r"(b[0]), "r"(b[1]));
}

// Swizzled 64B-row smem offset: 4 chunks of 16B per row, chunk ^= (row>>1)&3.
__device__ __forceinline__ uint32_t swz(int row, int ch) {
    return (uint32_t)row * 64u + (uint32_t)((ch ^ ((row >> 1) & 3)) << 4);
}

// fp32 -> fp16 conversion pass (16B loads, 8B stores, coalesced).
__global__ void __launch_bounds__(256) cvt_kernel(const float4* __restrict__ in,
                                                  __half2* __restrict__ out, int n4)
{
    int i = blockIdx.x * blockDim.x + threadIdx.x;
    if (i >= n4) return;
    float4 v = in[i];
    out[2 * i]     = __floats2half2_rn(v.x, v.y);
    out[2 * i + 1] = __floats2half2_rn(v.z, v.w);
}

// Load one 128x32-half A tile (64B rows, swizzled). 2 cp.async/thread @256thr.
__device__ __forceinline__ void load_tileA(uint32_t sbase, const __half* g, int tid) {
#pragma unroll
    for (int i = 0; i < 2; ++i) {
        int s = tid + i * 256;          // 0..511
        int row = s >> 2, ch = s & 3;
        cp16s(sbase + swz(row, ch), g + (size_t)row * K + ch * 8);
    }
}
// Load one 64x32-half B tile. 1 cp.async/thread.
__device__ __forceinline__ void load_tileB(uint32_t sbase, const __half* g, int tid) {
    int row = tid >> 2, ch = tid & 3;
    cp16s(sbase + swz(row, ch), g + (size_t)row * K + ch * 8);
}

// fp16 tensor-core GEMM with ldmatrix fragments.
// DUAL: A=g_xh, W1=g_wzh, W2=g_whh -> gate epilogue -> g_ab (fp32 pairs)
// !DUAL: A=g_hh, W1=g_woh          -> + bias        -> outF
template <bool DUAL>
__global__ void __launch_bounds__(256)
gemm_h(const float* __restrict__ b1, const float* __restrict__ b2,
       float* __restrict__ outF)
{
    extern __shared__ __align__(1024) char smem[];
    const uint32_t sb = (uint32_t)__cvta_generic_to_shared(smem);

    const int tid  = threadIdx.x;
    const int lane = tid & 31;
    const int warp = tid >> 5;
    const int wm   = warp & 3;     // 4 warps along M (32 rows)
    const int wn   = warp >> 2;    // 2 warps along N (32 cols)
    const int gr   = lane >> 2;
    const int gc   = lane & 3;

    const int n0 = blockIdx.x * BN;   // x = N tile -> A reuse in L2 across CTAs
    const int m0 = blockIdx.y * BM;

    const __half* A  = DUAL ? (const __half*)g_xh  : (const __half*)g_hh;
    const __half* W1 = DUAL ? (const __half*)g_wzh : (const __half*)g_woh;

    constexpr int NB  = DUAL ? 1 + 2 : 1 + 1;       // tiles per stage (A + Ws)
    constexpr int STB = TILEA + (NB - 1) * TILEB;   // stage bytes

    float accZ[2][4][4];
    float accH[DUAL ? 2 : 1][4][4];
#pragma unroll
    for (int i = 0; i < 2; ++i)
#pragma unroll
        for (int j = 0; j < 4; ++j)
#pragma unroll
            for (int r = 0; r < 4; ++r) { accZ[i][j][r] = 0.f; if (DUAL) accH[i][j][r] = 0.f; }

    // Per-lane ldmatrix address components.
    // A frag (x4): row = wm*32 + i*16 + (lane&15), chunk = 2ks + (lane>>4)
    int arow[2], aswz[2];
#pragma unroll
    for (int i = 0; i < 2; ++i) {
        arow[i] = (wm * 32 + i * 16 + (lane & 15)) * 64;
        aswz[i] = ((wm * 32 + i * 16 + (lane & 15)) >> 1) & 3;
    }
    const int achi = lane >> 4;
    // B frag (x4 covers 2 n8 tiles): n = wn*32 + p*16 + ((lane>>4)<<3) + (lane&7),
    // chunk = 2ks + ((lane>>3)&1)
    int brow[2], bswz[2];
#pragma unroll
    for (int p = 0; p < 2; ++p) {
        int n = wn * 32 + p * 16 + ((lane >> 4) << 3) + (lane & 7);
        brow[p] = n * 64;
        bswz[p] = (n >> 1) & 3;
    }
    const int bchi = (lane >> 3) & 1;

    auto load_chunk = [&](int j, int stage) {
        const int ko = j * BKH;
        const uint32_t base = sb + (uint32_t)stage * STB;
        load_tileA(base, A + (size_t)m0 * K + ko, tid);
        load_tileB(base + TILEA, W1 + (size_t)n0 * K + ko, tid);
        if (DUAL)
            load_tileB(base + TILEA + TILEB, (const __half*)g_whh + (size_t)n0 * K + ko, tid);
        asm volatile("cp.async.commit_group;");
    };

#pragma unroll
    for (int j = 0; j < STAGES; ++j) load_chunk(j, j);

    for (int k = 0; k < NT; ++k) {
        asm volatile("cp.async.wait_group %0;" :: "n"(STAGES - 1));
        __syncthreads();
        const int st = k & (STAGES - 1);
        const uint32_t abase = sb + (uint32_t)st * STB;
        const uint32_t bbase1 = abase + TILEA;
        const uint32_t bbase2 = bbase1 + TILEB;

#pragma unroll
        for (int ks = 0; ks < 2; ++ks) {
            uint32_t afr[2][4];
#pragma unroll
            for (int i = 0; i < 2; ++i) {
                const int ch = 2 * ks + achi;
                ldmx4(afr[i], abase + arow[i] + (uint32_t)(((ch ^ aswz[i])) << 4));
            }
#pragma unroll
            for (int p = 0; p < 2; ++p) {
                const int ch = 2 * ks + bchi;
                const uint32_t boff = brow[p] + (uint32_t)(((ch ^ bswz[p])) << 4);
                uint32_t bf1[4];
                ldmx4(bf1, bbase1 + boff);
#pragma unroll
                for (int i = 0; i < 2; ++i) {
                    mma16(accZ[i][2 * p + 0], afr[i], bf1 + 0);
                    mma16(accZ[i][2 * p + 1], afr[i], bf1 + 2);
                }
                if (DUAL) {
                    uint32_t bf2[4];
                    ldmx4(bf2, bbase2 + boff);
#pragma unroll
                    for (int i = 0; i < 2; ++i) {
                        mma16(accH[i][2 * p + 0], afr[i], bf2 + 0);
                        mma16(accH[i][2 * p + 1], afr[i], bf2 + 2);
                    }
                }
            }
        }
        __syncthreads();
        const int jn = k + STAGES;
        if (jn < NT) load_chunk(jn, st);
    }

    // Epilogue
#pragma unroll
    for (int i = 0; i < 2; ++i)
#pragma unroll
        for (int j = 0; j < 4; ++j)
#pragma unroll
            for (int p = 0; p < 2; ++p) {
                const int row = m0 + wm * 32 + i * 16 + gr + p * 8;
                const int col = n0 + wn * 32 + j * 8 + gc * 2;
                if (DUAL) {
                    float kz0 = accZ[i][j][2 * p + 0] + __ldg(&b1[col]);
                    float kz1 = accZ[i][j][2 * p + 1] + __ldg(&b1[col + 1]);
                    float kh0 = accH[i][j][2 * p + 0] + __ldg(&b2[col]);
                    float kh1 = accH[i][j][2 * p + 1] + __ldg(&b2[col + 1]);
                    // g(x) = x>=0 ? x+0.5 : sigmoid(x)   (== exp(log_g))
                    float g0 = (kh0 >= 0.f) ? (kh0 + 0.5f) : sigm(kh0);
                    float g1 = (kh1 >= 0.f) ? (kh1 + 0.5f) : sigm(kh1);
                    float4 o;
                    o.x = sigm(-kz0);          // a_t
                    o.y = sigm(kz0) * g0;      // b_t
                    o.z = sigm(-kz1);
                    o.w = sigm(kz1) * g1;
                    *reinterpret_cast<float4*>(&g_ab[(size_t)row * Dh + col]) = o;
                } else {
                    float2 o;
                    o.x = accZ[i][j][2 * p + 0] + __ldg(&b1[col]);
                    o.y = accZ[i][j][2 * p + 1] + __ldg(&b1[col + 1]);
                    *reinterpret_cast<float2*>(&outF[(size_t)row * Dh + col]) = o;
                }
            }
}

// ---- Chunked parallel scan: h_t = a_t * h_{t-1} + b_t (fp32) ----
__global__ void __launch_bounds__(256) scan_p1()
{
    const int t     = blockIdx.x * blockDim.x + threadIdx.x;
    const int bh    = t & (NSEQ - 1);
    const int chunk = t >> 13;
    const int b  = bh >> 10;
    const int hh = bh & 1023;
    const size_t base = ((size_t)b * Ss + (size_t)chunk * CL) * Dh + hh;
    float A = 1.f, Bv = 0.f;
#pragma unroll 8
    for (int s = 0; s < CL; ++s) {
        float2 v = g_ab[base + (size_t)s * Dh];
        A  *= v.x;
        Bv  = fmaf(v.x, Bv, v.y);
    }
    g_comp[(size_t)chunk * NSEQ + bh] = make_float2(A, Bv);
}

__global__ void __launch_bounds__(256) scan_p2()
{
    const int bh = blockIdx.x * blockDim.x + threadIdx.x;
    float h = 0.f;
#pragma unroll
    for (int c = 0; c < NC; ++c) {
        const size_t idx = (size_t)c * NSEQ + bh;
        float2 cmp = g_comp[idx];
        g_carry[idx] = h;
        h = fmaf(cmp.x, h, cmp.y);
    }
}

__global__ void __launch_bounds__(256) scan_p3()
{
    const int t     = blockIdx.x * blockDim.x + threadIdx.x;
    const int bh    = t & (NSEQ - 1);
    const int chunk = t >> 13;
    const int b  = bh >> 10;
    const int hh = bh & 1023;
    const size_t base = ((size_t)b * Ss + (size_t)chunk * CL) * Dh + hh;
    float h = g_carry[(size_t)chunk * NSEQ + bh];
#pragma unroll 8
    for (int s = 0; s < CL; ++s) {
        const size_t idx = base + (size_t)s * Dh;
        float2 v = g_ab[idx];
        h = fmaf(v.x, h, v.y);
        g_hh[idx] = __float2half(h);
    }
}

extern "C" void kernel_launch(void* const* d_in, const int* in_sizes, int n_in,
                              void* d_out, int out_size)
{
    const float* x  = (const float*)d_in[0];
    const float* Wz = (const float*)d_in[1];
    const float* bz = (const float*)d_in[2];
    const float* Wh = (const float*)d_in[3];
    const float* bh = (const float*)d_in[4];
    const float* Wo = (const float*)d_in[5];
    const float* bo = (const float*)d_in[6];
    float* out = (float*)d_out;

    const int smem_dual   = STAGES * (TILEA + 2 * TILEB);  // 65536 B
    const int smem_single = STAGES * (TILEA + 1 * TILEB);  // 49152 B
    cudaFuncSetAttribute(gemm_h<true>,  cudaFuncAttributeMaxDynamicSharedMemorySize, smem_dual);
    cudaFuncSetAttribute(gemm_h<false>, cudaFuncAttributeMaxDynamicSharedMemorySize, smem_single);

    // 0) convert operands to fp16
    {
        __half2* xh;  cudaGetSymbolAddress((void**)&xh,  g_xh);
        __half2* wzh; cudaGetSymbolAddress((void**)&wzh, g_wzh);
        __half2* whh; cudaGetSymbolAddress((void**)&whh, g_whh);
        __half2* woh; cudaGetSymbolAddress((void**)&woh, g_woh);
        const int nx4 = (M * K) / 4;
        const int nw4 = (Dh * K) / 4;
        cvt_kernel<<<(nx4 + 255) / 256, 256>>>((const float4*)x,  xh,  nx4);
        cvt_kernel<<<(nw4 + 255) / 256, 256>>>((const float4*)Wz, wzh, nw4);
        cvt_kernel<<<(nw4 + 255) / 256, 256>>>((const float4*)Wh, whh, nw4);
        cvt_kernel<<<(nw4 + 255) / 256, 256>>>((const float4*)Wo, woh, nw4);
    }

    dim3 grid(Dh / BN, M / BM);   // (16, 256): x = N tile for A reuse in L2

    // 1) fused dual fp16 GEMM + gate nonlinearities -> (a, b) pairs
    gemm_h<true><<<grid, 256, smem_dual>>>(bz, bh, nullptr);

    // 2) chunked parallel scan (fp32)
    scan_p1<<<(NC * NSEQ) / 256, 256>>>();
    scan_p2<<<NSEQ / 256, 256>>>();
    scan_p3<<<(NC * NSEQ) / 256, 256>>>();

    // 3) output projection with bias
    gemm_h<false><<<grid, 256, smem_single>>>(bo, nullptr, out);
}